// round 9
// baseline (speedup 1.0000x reference)
#include <cuda_runtime.h>

// LengthRegulator, fused single-wave kernel:
// ys[b, f, :] = xs[b, i, :] where cum[b,i-1] <= f < cum[b,i], else 0.
//
// 256 blocks (one wave at 2 blocks/SM). Each block: shuffle-scan ds[b,:],
// scatter its 128-frame chunk's frame->row map into shared (-1 = zero), then
// 4 groups of 6-deep phased LDG.128/STG.128 copies.

#define BATCH   8
#define TIN     512
#define TOUT    4096
#define DIM4    96                  // 384/4 float4 per row
#define FPB     128                 // frames per block
#define THREADS 512
#define GROUPS  4
#define ILP     6                   // (FPB*DIM4)/(THREADS*GROUPS) = 6

__global__ __launch_bounds__(THREADS, 2)
void lr_fused(const float4* __restrict__ xs,
              const int* __restrict__ ds,
              float4* __restrict__ out)
{
    __shared__ int s_wsum[16];
    __shared__ int s_map[FPB];

    const int b      = blockIdx.x;
    const int frame0 = blockIdx.y * FPB;
    const int tid    = threadIdx.x;
    const int lane   = tid & 31;
    const int wid    = tid >> 5;

    const int d = ds[b * TIN + tid];

    // warp-level inclusive scan (validated R4-R6)
    int v = d;
#pragma unroll
    for (int off = 1; off < 32; off <<= 1) {
        int n = __shfl_up_sync(0xffffffffu, v, off);
        if (lane >= off) v += n;
    }
    if (lane == 31) s_wsum[wid] = v;
    if (tid < FPB)  s_map[tid] = -1;
    __syncthreads();

    if (wid == 0 && lane < 16) {
        int w = s_wsum[lane];
#pragma unroll
        for (int off = 1; off < 16; off <<= 1) {
            int n = __shfl_up_sync(0x0000ffffu, w, off);
            if (lane >= off) w += n;
        }
        s_wsum[lane] = w;           // inclusive warp-prefix
    }
    __syncthreads();

    const int cum  = v + (wid > 0 ? s_wsum[wid - 1] : 0);
    const int left = cum - d;

    // scatter this row's frames intersected with our chunk (disjoint writes)
    int lo = left < frame0 ? frame0 : left;
    int hi = cum  > frame0 + FPB ? frame0 + FPB : cum;
    for (int f = lo; f < hi; f++)
        s_map[f - frame0] = tid;
    __syncthreads();

    const float4* __restrict__ xsb  = xs  + (size_t)b * TIN  * DIM4;
    float4* __restrict__       outb = out + (size_t)(b * TOUT + frame0) * DIM4;

#pragma unroll
    for (int g = 0; g < GROUPS; g++) {
        int fl[ILP], sl[ILP], row[ILP];
#pragma unroll
        for (int it = 0; it < ILP; it++) {
            const int item = (g * ILP + it) * THREADS + tid;
            fl[it]  = item / DIM4;
            sl[it]  = item - fl[it] * DIM4;
            row[it] = s_map[fl[it]];
        }

        float4 val[ILP];
#pragma unroll
        for (int it = 0; it < ILP; it++) {
            val[it] = make_float4(0.f, 0.f, 0.f, 0.f);
            if (row[it] >= 0)
                val[it] = xsb[row[it] * DIM4 + sl[it]];
        }

#pragma unroll
        for (int it = 0; it < ILP; it++)
            outb[fl[it] * DIM4 + sl[it]] = val[it];
    }
}

extern "C" void kernel_launch(void* const* d_in, const int* in_sizes, int n_in,
                              void* d_out, int out_size)
{
    const float* xs = (const float*)d_in[0];
    const int*   ds = (const int*)d_in[1];
    float*       out = (float*)d_out;

    dim3 grid(BATCH, TOUT / FPB);   // 8 x 32 = 256 blocks, single wave
    lr_fused<<<grid, THREADS>>>((const float4*)xs, ds, (float4*)out);
}

// round 10
// speedup vs baseline: 1.1429x; 1.1429x over previous
#include <cuda_runtime.h>

// LengthRegulator, fused, warp-per-frame:
// ys[b, f, :] = xs[b, i, :] where cum[b,i-1] <= f < cum[b,i], else 0.
//
// Each block: shuffle-scan ds[b,:], scatter its 64-frame window's
// frame->row map into shared (-1 = zero). Copy phase: each warp owns 4
// consecutive frames; re-loads the 1536B source row only when the row id
// changes (mean run length 3.5 -> ~3.5x fewer load wavefronts).

#define BATCH   8
#define TIN     512
#define TOUT    4096
#define DIM4    96                  // 384/4 float4 per row
#define FPB     64                  // frames per block
#define THREADS 512                 // 16 warps
#define FPW     (FPB / 16)          // 4 frames per warp

__device__ float4 g_zero[DIM4];     // stays zero (never written)

__global__ __launch_bounds__(THREADS, 3)
void lr_fused(const float4* __restrict__ xs,
              const int* __restrict__ ds,
              float4* __restrict__ out)
{
    __shared__ int s_wsum[16];
    __shared__ int s_map[FPB];

    const int b      = blockIdx.x;
    const int frame0 = blockIdx.y * FPB;
    const int tid    = threadIdx.x;
    const int lane   = tid & 31;
    const int wid    = tid >> 5;

    const int d = ds[b * TIN + tid];

    // warp-level inclusive scan (validated R4-R7)
    int v = d;
#pragma unroll
    for (int off = 1; off < 32; off <<= 1) {
        int n = __shfl_up_sync(0xffffffffu, v, off);
        if (lane >= off) v += n;
    }
    if (lane == 31) s_wsum[wid] = v;
    if (tid < FPB)  s_map[tid] = -1;
    __syncthreads();

    if (wid == 0 && lane < 16) {
        int w = s_wsum[lane];
#pragma unroll
        for (int off = 1; off < 16; off <<= 1) {
            int n = __shfl_up_sync(0x0000ffffu, w, off);
            if (lane >= off) w += n;
        }
        s_wsum[lane] = w;           // inclusive warp-prefix
    }
    __syncthreads();

    const int cum  = v + (wid > 0 ? s_wsum[wid - 1] : 0);
    const int left = cum - d;

    // scatter this row's frames intersected with our window (disjoint writes)
    int lo = left < frame0 ? frame0 : left;
    int hi = cum  > frame0 + FPB ? frame0 + FPB : cum;
    for (int f = lo; f < hi; f++)
        s_map[f - frame0] = tid;
    __syncthreads();

    // ---- copy: warp w owns frames [frame0 + w*FPW, +FPW) ----
    const float4* __restrict__ xsb = xs + (size_t)b * TIN * DIM4;
    const int fbase = wid * FPW;
    float4* __restrict__ o =
        out + (size_t)(b * TOUT + frame0 + fbase) * DIM4 + lane;

    int prev_row = -2;              // sentinel: != any valid row or -1
    float4 a0, a1, a2;
#pragma unroll
    for (int k = 0; k < FPW; k++) {
        const int row = s_map[fbase + k];          // warp-uniform
        if (row != prev_row) {                     // uniform branch
            const float4* p = (row >= 0) ? (xsb + row * DIM4) : g_zero;
            a0 = p[lane];
            a1 = p[lane + 32];
            a2 = p[lane + 64];
            prev_row = row;
        }
        o[k * DIM4]      = a0;      // compile-time immediate offsets
        o[k * DIM4 + 32] = a1;
        o[k * DIM4 + 64] = a2;
    }
}

extern "C" void kernel_launch(void* const* d_in, const int* in_sizes, int n_in,
                              void* d_out, int out_size)
{
    const float* xs = (const float*)d_in[0];
    const int*   ds = (const int*)d_in[1];
    float*       out = (float*)d_out;

    dim3 grid(BATCH, TOUT / FPB);   // 8 x 64 = 512 blocks
    lr_fused<<<grid, THREADS>>>((const float4*)xs, ds, (float4*)out);
}